// round 14
// baseline (speedup 1.0000x reference)
#include <cuda_runtime.h>
#include <cuda_bf16.h>
#include <cuda_fp16.h>
#include <cstdint>

#define Bn 256
#define Tn 256
#define Cn 256
#define Hn 64

// ---------------- scratch ----------------
__device__ __align__(16) __nv_bfloat16 g_qh[Bn*Tn*Hn];
__device__ __align__(16) __nv_bfloat16 g_ql[Bn*Tn*Hn];
__device__ __align__(16) __nv_bfloat16 g_kh[Bn*Tn*Hn];
__device__ __align__(16) __nv_bfloat16 g_kl[Bn*Tn*Hn];
__device__ __align__(16) __nv_bfloat16 g_vh[Bn*Tn*Hn];
__device__ __align__(16) __nv_bfloat16 g_vl[Bn*Tn*Hn];
__device__ __align__(16) __half g_ps[(long)Bn*Tn*256];  // P s-layout, fp16
__device__ __align__(16) __nv_bfloat16 g_Wh[4*192*72];
__device__ __align__(16) __nv_bfloat16 g_Wl[4*192*72];
__device__ __align__(16) __nv_bfloat16 g_Eh[256*72];
__device__ __align__(16) __nv_bfloat16 g_El[256*72];

// ---------------- helpers ----------------
__device__ __forceinline__ uint32_t smem_u32(const void* p) {
    uint32_t a;
    asm("{ .reg .u64 t; cvta.to.shared.u64 t, %1; cvt.u32.u64 %0, t; }" : "=r"(a) : "l"(p));
    return a;
}
__device__ __forceinline__ void cp16(uint32_t sdst, const void* gsrc) {
    asm volatile("cp.async.cg.shared.global [%0], [%1], 16;" :: "r"(sdst), "l"(gsrc));
}
#define CP_COMMIT() asm volatile("cp.async.commit_group;" ::: "memory")
#define CP_WAIT(n)  asm volatile("cp.async.wait_group %0;" :: "n"(n) : "memory")
__device__ __forceinline__ void mma_bf16(float* c, const uint32_t* a, const uint32_t* b) {
    asm volatile(
        "mma.sync.aligned.m16n8k16.row.col.f32.bf16.bf16.f32 "
        "{%0,%1,%2,%3}, {%4,%5,%6,%7}, {%8,%9}, {%0,%1,%2,%3};"
        : "+f"(c[0]), "+f"(c[1]), "+f"(c[2]), "+f"(c[3])
        : "r"(a[0]), "r"(a[1]), "r"(a[2]), "r"(a[3]), "r"(b[0]), "r"(b[1]));
}
__device__ __forceinline__ void ldsm4(uint32_t* r, uint32_t addr) {
    asm volatile("ldmatrix.sync.aligned.m8n8.x4.shared.b16 {%0,%1,%2,%3}, [%4];"
        : "=r"(r[0]), "=r"(r[1]), "=r"(r[2]), "=r"(r[3]) : "r"(addr));
}
__device__ __forceinline__ void ldsm4t(uint32_t* r, uint32_t addr) {
    asm volatile("ldmatrix.sync.aligned.m8n8.x4.trans.shared.b16 {%0,%1,%2,%3}, [%4];"
        : "=r"(r[0]), "=r"(r[1]), "=r"(r[2]), "=r"(r[3]) : "r"(addr));
}
__device__ __forceinline__ void split_bf(float v, __nv_bfloat16& h, __nv_bfloat16& l) {
    h = __float2bfloat16(v);
    l = __float2bfloat16(v - __bfloat162float(h));
}
__device__ __forceinline__ uint32_t pk(__nv_bfloat16 a, __nv_bfloat16 b) {
    return (uint32_t)__bfloat16_as_ushort(a) | ((uint32_t)__bfloat16_as_ushort(b) << 16);
}

// ---------------------------------------------------------------------------
// Setup: build hi/lo pad-72 images of [Wq|Wk*0.125|Wv] and E.
// ---------------------------------------------------------------------------
__global__ __launch_bounds__(256) void setup_kernel(
    const float* __restrict__ Wk, const float* __restrict__ Wq,
    const float* __restrict__ Wv, const float* __restrict__ E)
{
    int id = blockIdx.x * 256 + threadIdx.x;
    if (id < 4 * 192 * 72) {
        int kt = id / (192 * 72);
        int rem = id % (192 * 72);
        int n = rem / 72, k = rem % 72;
        float v = 0.f;
        if (k < 64) {
            int which = n >> 6, col = n & 63;
            const float* W = (which == 0) ? Wq : (which == 1) ? Wk : Wv;
            v = W[(kt * 64 + k) * Hn + col];
            if (which == 1) v *= 0.125f;
        }
        __nv_bfloat16 h, l;
        split_bf(v, h, l);
        g_Wh[id] = h;
        g_Wl[id] = l;
    } else {
        int id2 = id - 4 * 192 * 72;
        if (id2 < 256 * 72) {
            int d = id2 / 72, k = id2 % 72;
            float v = (k < 64) ? E[d * Hn + k] : 0.f;
            __nv_bfloat16 h, l;
            split_bf(v, h, l);
            g_Eh[id2] = h;
            g_El[id2] = l;
        }
    }
}

// ---------------------------------------------------------------------------
// Fused qkv GEMM (bf16x3, ldmatrix), cp.async DOUBLE-BUFFERED B images.
// grid=512, block=512. smem: A 2x9216 + B 2 bufs x 2 x 13824 = 73728 bf16.
// ---------------------------------------------------------------------------
__global__ __launch_bounds__(512, 1) void qkv_kernel(const float* __restrict__ x)
{
    extern __shared__ __nv_bfloat16 smb[];
    __nv_bfloat16* Ah = smb;                        // 128*72
    __nv_bfloat16* Al = Ah + 128 * 72;
    __nv_bfloat16* Bbuf = Al + 128 * 72;            // [buf][h/l][192*72]

    const int row0 = blockIdx.x * 128;
    const int tid = threadIdx.x, w = tid >> 5, lane = tid & 31;
    const int wm = w >> 2, wn = w & 3;
    const int g = lane >> 2, l2 = lane & 3;

    const uint32_t aH = smem_u32(Ah), aL = smem_u32(Al);
    const uint32_t bBase = smem_u32(Bbuf);
    const int arow = wm * 32 + (lane & 15);
    const int acol = (lane >> 4) * 8;
    const int brow = wn * 48 + (lane & 7) + (lane >> 4) * 8;
    const int bcol = ((lane >> 3) & 1) * 8;

    // issue B copies for chunk `ct` into buffer `buf`
    auto issue_B = [&](int buf, int ct) {
        uint32_t dsth = bBase + buf * (2 * 192 * 72 * 2);
        uint32_t dstl = dsth + 192 * 72 * 2;
        const __nv_bfloat16* sh = g_Wh + ct * 192 * 72;
        const __nv_bfloat16* sl = g_Wl + ct * 192 * 72;
        #pragma unroll
        for (int idx = tid; idx < 1728; idx += 512) {
            cp16(dsth + idx * 16, sh + idx * 8);
            cp16(dstl + idx * 16, sl + idx * 8);
        }
    };

    issue_B(0, 0);
    CP_COMMIT();

    float acc[2][6][4] = {};

    for (int ct = 0; ct < 4; ct++) {
        const int buf = ct & 1;
        float4 xv[4];
        #pragma unroll
        for (int i = 0; i < 4; i++) {
            int f = tid + i * 512;
            int r = f >> 4, c4 = (f & 15) << 2;
            xv[i] = *(const float4*)(x + (row0 + r) * Cn + ct * 64 + c4);
        }
        __syncthreads();   // prior chunk's ldmatrix reads done (A + B[buf^1])

        #pragma unroll
        for (int i = 0; i < 4; i++) {
            int f = tid + i * 512;
            int r = f >> 4, c4 = (f & 15) << 2;
            __nv_bfloat16 h0, l0, h1, l1, h2, l2b, h3, l3;
            split_bf(xv[i].x, h0, l0);
            split_bf(xv[i].y, h1, l1);
            split_bf(xv[i].z, h2, l2b);
            split_bf(xv[i].w, h3, l3);
            uint2 uh = {pk(h0, h1), pk(h2, h3)};
            uint2 ul = {pk(l0, l1), pk(l2b, l3)};
            *(uint2*)(Ah + r * 72 + c4) = uh;
            *(uint2*)(Al + r * 72 + c4) = ul;
        }
        if (ct < 3) {
            issue_B(buf ^ 1, ct + 1);
            CP_COMMIT();
            CP_WAIT(1);    // current buf's copies done; next may be in flight
        } else {
            CP_WAIT(0);
        }
        __syncthreads();

        const uint32_t bH = bBase + buf * (2 * 192 * 72 * 2);
        const uint32_t bL = bH + 192 * 72 * 2;
        #pragma unroll
        for (int ks = 0; ks < 64; ks += 16) {
            uint32_t ah[2][4], al[2][4], bh[3][4], bl[3][4];
            #pragma unroll
            for (int mi = 0; mi < 2; mi++) {
                uint32_t off = ((arow + mi * 16) * 72 + ks + acol) * 2;
                ldsm4(ah[mi], aH + off);
                ldsm4(al[mi], aL + off);
            }
            #pragma unroll
            for (int nj = 0; nj < 3; nj++) {
                uint32_t off = ((brow + nj * 16) * 72 + ks + bcol) * 2;
                ldsm4(bh[nj], bH + off);
                ldsm4(bl[nj], bL + off);
            }
            #pragma unroll
            for (int mi = 0; mi < 2; mi++)
                #pragma unroll
                for (int ni = 0; ni < 6; ni++) {
                    const uint32_t* ph = &bh[ni >> 1][(ni & 1) * 2];
                    const uint32_t* pl = &bl[ni >> 1][(ni & 1) * 2];
                    mma_bf16(acc[mi][ni], ah[mi], ph);
                    mma_bf16(acc[mi][ni], ah[mi], pl);
                    mma_bf16(acc[mi][ni], al[mi], ph);
                }
        }
    }

    #pragma unroll
    for (int mi = 0; mi < 2; mi++) {
        int rr = row0 + wm * 32 + mi * 16 + g;
        #pragma unroll
        for (int ni = 0; ni < 6; ni++) {
            int n = wn * 48 + ni * 8 + l2 * 2;
            __nv_bfloat16* dh = (n < 64) ? g_qh : (n < 128) ? g_kh : g_vh;
            __nv_bfloat16* dl = (n < 64) ? g_ql : (n < 128) ? g_kl : g_vl;
            int col = n & 63;
            __nv_bfloat16 h0, l0, h1, l1, h2, l2b, h3, l3;
            split_bf(acc[mi][ni][0], h0, l0);
            split_bf(acc[mi][ni][1], h1, l1);
            split_bf(acc[mi][ni][2], h2, l2b);
            split_bf(acc[mi][ni][3], h3, l3);
            *(uint32_t*)(dh + rr * 64 + col)       = pk(h0, h1);
            *(uint32_t*)(dl + rr * 64 + col)       = pk(l0, l1);
            *(uint32_t*)(dh + (rr + 8) * 64 + col) = pk(h2, h3);
            *(uint32_t*)(dl + (rr + 8) * 64 + col) = pk(l2b, l3);
        }
    }
}

// ---------------------------------------------------------------------------
// pos: P = q @ E^T (bf16x3, ldmatrix, cp.async copies). grid=(1024,2), blk=256.
// ---------------------------------------------------------------------------
__global__ __launch_bounds__(256) void pos_kernel()
{
    const int row0  = blockIdx.x * 64;
    const int t0    = row0 & 255;
    const int nbase = blockIdx.y * 128;
    const int dmin  = 192 - t0;
    if (nbase + 127 < dmin) return;

    extern __shared__ __nv_bfloat16 smb[];
    __nv_bfloat16* Ah = smb;
    __nv_bfloat16* Al = Ah + 64 * 72;
    __nv_bfloat16* Eh = Al + 64 * 72;
    __nv_bfloat16* El = Eh + 128 * 72;
    float* stage = (float*)smb;       // reused after compute

    const int tid = threadIdx.x, w = tid >> 5, lane = tid & 31;
    const int wm = w >> 2, wn = w & 3;
    const int g = lane >> 2, l2 = lane & 3;

    const uint32_t aHs = smem_u32(Ah), aLs = smem_u32(Al);
    const uint32_t eHs = smem_u32(Eh), eLs = smem_u32(El);

    // cp.async copies: q (512 uint4 per array), E (1152 per array)
    #pragma unroll
    for (int i = 0; i < 2; i++) {
        int f = tid + i * 256;
        int r = f >> 3, c = (f & 7) * 8;
        cp16(aHs + (r * 72 + c) * 2, g_qh + (row0 + r) * 64 + c);
        cp16(aLs + (r * 72 + c) * 2, g_ql + (row0 + r) * 64 + c);
    }
    #pragma unroll
    for (int idx = tid; idx < 1152; idx += 256) {
        cp16(eHs + idx * 16, g_Eh + nbase * 72 + idx * 8);
        cp16(eLs + idx * 16, g_El + nbase * 72 + idx * 8);
    }
    CP_COMMIT();
    CP_WAIT(0);
    __syncthreads();

    const bool live = (nbase + wn * 32 + 31 >= dmin);
    float acc[2][4][4] = {};
    if (live) {
        const int arow = wm * 32 + (lane & 15);
        const int acol = (lane >> 4) * 8;
        const int brow = wn * 32 + (lane & 7) + (lane >> 4) * 8;
        const int bcol = ((lane >> 3) & 1) * 8;
        #pragma unroll
        for (int ks = 0; ks < 64; ks += 16) {
            uint32_t ah[2][4], al[2][4], bh[2][4], bl[2][4];
            #pragma unroll
            for (int mi = 0; mi < 2; mi++) {
                uint32_t off = ((arow + mi * 16) * 72 + ks + acol) * 2;
                ldsm4(ah[mi], aHs + off);
                ldsm4(al[mi], aLs + off);
            }
            #pragma unroll
            for (int nj = 0; nj < 2; nj++) {
                uint32_t off = ((brow + nj * 16) * 72 + ks + bcol) * 2;
                ldsm4(bh[nj], eHs + off);
                ldsm4(bl[nj], eLs + off);
            }
            #pragma unroll
            for (int mi = 0; mi < 2; mi++)
                #pragma unroll
                for (int ni = 0; ni < 4; ni++) {
                    const uint32_t* ph = &bh[ni >> 1][(ni & 1) * 2];
                    const uint32_t* pl = &bl[ni >> 1][(ni & 1) * 2];
                    mma_bf16(acc[mi][ni], ah[mi], ph);
                    mma_bf16(acc[mi][ni], ah[mi], pl);
                    mma_bf16(acc[mi][ni], al[mi], ph);
                }
        }
    }
    __syncthreads();

    if (live) {
        #pragma unroll
        for (int mi = 0; mi < 2; mi++) {
            int rl = wm * 32 + mi * 16 + g;
            #pragma unroll
            for (int ni = 0; ni < 4; ni++) {
                int dl = wn * 32 + ni * 8 + l2 * 2;
                stage[rl * 132 + dl]           = acc[mi][ni][0];
                stage[rl * 132 + dl + 1]       = acc[mi][ni][1];
                stage[(rl + 8) * 132 + dl]     = acc[mi][ni][2];
                stage[(rl + 8) * 132 + dl + 1] = acc[mi][ni][3];
            }
        }
    }
    __syncthreads();

    // aligned fp16 s-layout store: 4 threads per row
    {
        int r = tid >> 2, j = tid & 3;
        int t = (row0 + r) & 255;
        long grow = (long)(row0 + r) * 256;
        int slr = nbase + t - 255;
        int s_hi = slr + 128;
        if (s_hi > 0) {
            int s_lo = slr < 0 ? 0 : slr;
            int a0 = (s_lo + 7) & ~7;
            int a1;
            if (nbase == 128) {
                a1 = (s_hi + 7) & ~7;
                if (a1 > 256) a1 = 256;
            } else {
                a1 = s_hi & ~7;
            }
            const float* srow = stage + r * 132 - slr;
            for (int hs = s_lo + j; hs < a0 && hs < s_hi; hs += 4)
                g_ps[grow + hs] = __float2half(srow[hs]);
            for (int s8 = a0 + j * 8; s8 < a1; s8 += 32) {
                __half tmp[8];
                #pragma unroll
                for (int e = 0; e < 8; e++) tmp[e] = __float2half(srow[s8 + e]);
                *(uint4*)(g_ps + grow + s8) = *(const uint4*)tmp;
            }
            if (nbase == 0) {
                for (int ts = a1 + j; ts < s_hi; ts += 4)
                    g_ps[grow + ts] = __float2half(srow[ts]);
            }
        }
    }
}

// ---------------------------------------------------------------------------
// attention via bf16x3 mma, cp.async q/k/v copies overlapped with compute.
// grid=(256,4), block=512. Heavy tiles first.
// ---------------------------------------------------------------------------
__global__ __launch_bounds__(512, 1) void attn_kernel(float* __restrict__ out)
{
    extern __shared__ char smc[];
    float* sc = (float*)smc;                                   // 64*264 f32
    __nv_bfloat16* wh = (__nv_bfloat16*)(smc + 64 * 264 * 4);  // 64*264
    __nv_bfloat16* wl = wh + 64 * 264;
    __nv_bfloat16* qh = wl + 64 * 264;                         // 64*72
    __nv_bfloat16* ql = qh + 64 * 72;
    __nv_bfloat16* kh = ql + 64 * 72;                          // 256*72
    __nv_bfloat16* kl = kh + 256 * 72;

    const int b  = blockIdx.x;
    const int tt = 3 - blockIdx.y;          // heavy first
    const int t0 = tt * 64;
    const int nst = tt + 1;
    const int send = nst * 64;
    const int tid = threadIdx.x, w = tid >> 5, lane = tid & 31;
    const int g = lane >> 2, l2 = lane & 3;

    const uint32_t qHa = smem_u32(qh), qLa = smem_u32(ql);
    const uint32_t kHa = smem_u32(kh), kLa = smem_u32(kl);
    const uint32_t wHa = smem_u32(wh), wLa = smem_u32(wl);

    // ---- phase A: cp.async q/k copies; P prefill overlaps them ----
    {
        int r = tid >> 3, c = (tid & 7) * 8;
        cp16(qHa + (r * 72 + c) * 2, g_qh + ((long)(b * Tn + t0 + r)) * 64 + c);
        cp16(qLa + (r * 72 + c) * 2, g_ql + ((long)(b * Tn + t0 + r)) * 64 + c);
    }
    for (int f = tid; f < send * 8; f += 512) {
        int r = f >> 3, c = (f & 7) * 8;
        cp16(kHa + (r * 72 + c) * 2, g_kh + ((long)(b * Tn + r)) * 64 + c);
        cp16(kLa + (r * 72 + c) * 2, g_kl + ((long)(b * Tn + r)) * 64 + c);
    }
    CP_COMMIT();

    #pragma unroll
    for (int i = 0; i < 4; i++) {
        int f = tid + i * 512;
        int r = f >> 5, s8 = (f & 31) << 3;
        if (s8 < send) {
            int t = t0 + r;
            uint4 pv = *(const uint4*)(g_ps + ((long)(b * Tn + t)) * 256 + s8);
            const __half* ph = (const __half*)&pv;
            float o[8];
            #pragma unroll
            for (int e = 0; e < 8; e++)
                o[e] = (s8 + e <= t) ? __half2float(ph[e]) : -1e30f;
            *(float4*)&sc[r * 264 + s8]     = make_float4(o[0], o[1], o[2], o[3]);
            *(float4*)&sc[r * 264 + s8 + 4] = make_float4(o[4], o[5], o[6], o[7]);
        }
    }
    CP_WAIT(0);
    __syncthreads();

    // ---- score phase: warps 2m x 8n, one 32x32 tile each ----
    {
        const int wm = w >> 3, wn = w & 7;
        const int cb = wn * 32;
        if (cb < send && cb <= t0 + wm * 32 + 31) {
            const int arow = wm * 32 + (lane & 15);
            const int acol = (lane >> 4) * 8;
            const int brow = cb + (lane & 7) + (lane >> 4) * 8;
            const int bcol = ((lane >> 3) & 1) * 8;
            float acc[2][4][4] = {};
            #pragma unroll
            for (int ks = 0; ks < 4; ks++) {
                uint32_t ah[2][4], al[2][4], bh[2][4], bl[2][4];
                #pragma unroll
                for (int mi = 0; mi < 2; mi++) {
                    uint32_t off = ((arow + mi * 16) * 72 + ks * 16 + acol) * 2;
                    ldsm4(ah[mi], qHa + off);
                    ldsm4(al[mi], qLa + off);
                }
                #pragma unroll
                for (int nj = 0; nj < 2; nj++) {
                    uint32_t off = ((brow + nj * 16) * 72 + ks * 16 + bcol) * 2;
                    ldsm4(bh[nj], kHa + off);
                    ldsm4(bl[nj], kLa + off);
                }
                #pragma unroll
                for (int mi = 0; mi < 2; mi++)
                    #pragma unroll
                    for (int ni = 0; ni < 4; ni++) {
                        const uint32_t* ph = &bh[ni >> 1][(ni & 1) * 2];
                        const uint32_t* pl = &bl[ni >> 1][(ni & 1) * 2];
                        mma_bf16(acc[mi][ni], ah[mi], ph);
                        mma_bf16(acc[mi][ni], ah[mi], pl);
                        mma_bf16(acc[mi][ni], al[mi], ph);
                    }
            }
            #pragma unroll
            for (int mi = 0; mi < 2; mi++)
                #pragma unroll
                for (int ni = 0; ni < 4; ni++) {
                    int rloc = wm * 32 + mi * 16 + g;
                    int sbase = cb + ni * 8 + l2 * 2;
                    #pragma unroll
                    for (int hf = 0; hf < 2; hf++) {
                        int row = rloc + hf * 8;
                        float2 cur = *(float2*)&sc[row * 264 + sbase];
                        cur.x += acc[mi][ni][hf * 2];
                        cur.y += acc[mi][ni][hf * 2 + 1];
                        *(float2*)&sc[row * 264 + sbase] = cur;
                    }
                }
        }
    }
    __syncthreads();

    // ---- v copies via cp.async (overlap softmax) ----
    for (int f = tid; f < send * 8; f += 512) {
        int r = f >> 3, c = (f & 7) * 8;
        cp16(kHa + (r * 72 + c) * 2, g_vh + ((long)(b * Tn + r)) * 64 + c);
        cp16(kLa + (r * 72 + c) * 2, g_vl + ((long)(b * Tn + r)) * 64 + c);
    }
    CP_COMMIT();

    // ---- softmax: 16 warps x 4 rows, bf16 hi/lo weight emit ----
    for (int r = w * 4; r < w * 4 + 4; r++) {
        float m = -1e30f;
        for (int i = 0; i < nst; i++) {
            float2 v = *(const float2*)&sc[r * 264 + i * 64 + lane * 2];
            m = fmaxf(m, fmaxf(v.x, v.y));
        }
        #pragma unroll
        for (int o = 16; o; o >>= 1) m = fmaxf(m, __shfl_xor_sync(0xffffffffu, m, o));
        float sum = 0.f;
        for (int i = 0; i < nst; i++) {
            float2 v = *(const float2*)&sc[r * 264 + i * 64 + lane * 2];
            v.x = __expf(v.x - m);
            v.y = __expf(v.y - m);
            sum += v.x + v.y;
            *(float2*)&sc[r * 264 + i * 64 + lane * 2] = v;
        }
        #pragma unroll
        for (int o = 16; o; o >>= 1) sum += __shfl_xor_sync(0xffffffffu, sum, o);
        float inv = 1.0f / sum;
        for (int i = 0; i < nst; i++) {
            float2 e = *(const float2*)&sc[r * 264 + i * 64 + lane * 2];
            float w0 = e.x * inv, w1 = e.y * inv;
            __nv_bfloat16 h0, l0, h1, l1;
            split_bf(w0, h0, l0);
            split_bf(w1, h1, l1);
            *(uint32_t*)&wh[r * 264 + i * 64 + lane * 2] = pk(h0, h1);
            *(uint32_t*)&wl[r * 264 + i * 64 + lane * 2] = pk(l0, l1);
        }
    }
    CP_WAIT(0);
    __syncthreads();

    // ---- out = wei @ v : split-K over warps (2m x 2n x 4k) ----
    {
        const int wk = w & 3;
        const int wn2 = (w >> 2) & 1;
        const int wm2 = w >> 3;
        if (wk < nst) {
            const int arow = wm2 * 32 + (lane & 15);
            const int acol = (lane >> 4) * 8;
            const int vrow = (lane & 7) + ((lane >> 3) & 1) * 8;
            const int vcol = wn2 * 32 + (lane >> 4) * 8;
            float oacc[2][4][4] = {};
            #pragma unroll
            for (int ks = 0; ks < 4; ks++) {
                uint32_t aw[2][4], awl[2][4], bvh[2][4], bvl[2][4];
                #pragma unroll
                for (int mi = 0; mi < 2; mi++) {
                    uint32_t aoff = ((arow + mi * 16) * 264 + wk * 64 + ks * 16 + acol) * 2;
                    ldsm4(aw[mi],  wHa + aoff);
                    ldsm4(awl[mi], wLa + aoff);
                }
                #pragma unroll
                for (int nj = 0; nj < 2; nj++) {
                    uint32_t voff = ((wk * 64 + ks * 16 + vrow) * 72 + vcol + nj * 16) * 2;
                    ldsm4t(bvh[nj], kHa + voff);
                    ldsm4t(bvl[nj], kLa + voff);
                }
                #pragma unroll
                for (int mi = 0; mi < 2; mi++)
                    #pragma unroll
                    for (int ni = 0; ni < 4; ni++) {
                        const uint32_t* ph = &bvh[ni >> 1][(ni & 1) * 2];
                        const uint32_t* pl = &bvl[ni >> 1][(ni & 1) * 2];
                        mma_bf16(oacc[mi][ni], aw[mi],  ph);
                        mma_bf16(oacc[mi][ni], aw[mi],  pl);
                        mma_bf16(oacc[mi][ni], awl[mi], ph);
                    }
            }
            float* slice = sc + wk * 4096;
            #pragma unroll
            for (int mi = 0; mi < 2; mi++)
                #pragma unroll
                for (int ni = 0; ni < 4; ni++) {
                    int row = wm2 * 32 + mi * 16 + g;
                    int col = wn2 * 32 + ni * 8 + l2 * 2;
                    float2 o0 = {oacc[mi][ni][0], oacc[mi][ni][1]};
                    float2 o1 = {oacc[mi][ni][2], oacc[mi][ni][3]};
                    *(float2*)&slice[row * 64 + col] = o0;
                    *(float2*)&slice[(row + 8) * 64 + col] = o1;
                }
        }
    }
    __syncthreads();

    // ---- reduce nst slices and store ----
    #pragma unroll
    for (int i = 0; i < 8; i++) {
        int idx = tid + i * 512;
        float s = sc[idx];
        for (int j = 1; j < nst; j++) s += sc[j * 4096 + idx];
        int row = idx >> 6, col = idx & 63;
        out[((long)(b * Tn + t0 + row)) * Hn + col] = s;
    }
}

// ---------------------------------------------------------------------------
extern "C" void kernel_launch(void* const* d_in, const int* in_sizes, int n_in,
                              void* d_out, int out_size)
{
    const float* x  = (const float*)d_in[0];
    const float* Wk = (const float*)d_in[1];
    const float* Wq = (const float*)d_in[2];
    const float* Wv = (const float*)d_in[3];
    const float* E  = (const float*)d_in[4];
    float* out = (float*)d_out;

    setup_kernel<<<288, 256>>>(Wk, Wq, Wv, E);

    const int qkv_sm = (2 * 128 * 72 + 4 * 192 * 72) * (int)sizeof(__nv_bfloat16); // 147456
    cudaFuncSetAttribute(qkv_kernel, cudaFuncAttributeMaxDynamicSharedMemorySize, qkv_sm);
    qkv_kernel<<<Bn * Tn / 128, 512, qkv_sm>>>(x);

    const int pos_sm = (2 * 64 * 72 + 2 * 128 * 72) * (int)sizeof(__nv_bfloat16);  // 55296
    cudaFuncSetAttribute(pos_kernel, cudaFuncAttributeMaxDynamicSharedMemorySize, pos_sm);
    pos_kernel<<<dim3(Bn * Tn / 64, 2), 256, pos_sm>>>();

    const int attn_sm = 64 * 264 * 4 + 2 * 64 * 264 * 2 + 2 * 64 * 72 * 2
                      + 2 * 256 * 72 * 2;                                          // 227328
    cudaFuncSetAttribute(attn_kernel, cudaFuncAttributeMaxDynamicSharedMemorySize, attn_sm);
    attn_kernel<<<dim3(Bn, Tn / 64), 512, attn_sm>>>(out);
}

// round 15
// speedup vs baseline: 1.3655x; 1.3655x over previous
#include <cuda_runtime.h>
#include <cuda_bf16.h>
#include <cuda_fp16.h>
#include <cstdint>

#define Bn 256
#define Tn 256
#define Cn 256
#define Hn 64

// ---------------- scratch ----------------
__device__ __align__(16) __nv_bfloat16 g_qh[Bn*Tn*Hn];
__device__ __align__(16) __nv_bfloat16 g_ql[Bn*Tn*Hn];
__device__ __align__(16) __nv_bfloat16 g_kh[Bn*Tn*Hn];
__device__ __align__(16) __nv_bfloat16 g_kl[Bn*Tn*Hn];
__device__ __align__(16) __nv_bfloat16 g_vh[Bn*Tn*Hn];
__device__ __align__(16) __nv_bfloat16 g_vl[Bn*Tn*Hn];
__device__ __align__(16) __half g_ps[(long)Bn*Tn*256];  // P s-layout, fp16
__device__ __align__(16) __nv_bfloat16 g_Wh[4*192*72];
__device__ __align__(16) __nv_bfloat16 g_Wl[4*192*72];
__device__ __align__(16) __nv_bfloat16 g_Eh[256*72];
__device__ __align__(16) __nv_bfloat16 g_El[256*72];

// ---------------- helpers ----------------
__device__ __forceinline__ uint32_t smem_u32(const void* p) {
    uint32_t a;
    asm("{ .reg .u64 t; cvta.to.shared.u64 t, %1; cvt.u32.u64 %0, t; }" : "=r"(a) : "l"(p));
    return a;
}
__device__ __forceinline__ void mma_bf16(float* c, const uint32_t* a, const uint32_t* b) {
    asm volatile(
        "mma.sync.aligned.m16n8k16.row.col.f32.bf16.bf16.f32 "
        "{%0,%1,%2,%3}, {%4,%5,%6,%7}, {%8,%9}, {%0,%1,%2,%3};"
        : "+f"(c[0]), "+f"(c[1]), "+f"(c[2]), "+f"(c[3])
        : "r"(a[0]), "r"(a[1]), "r"(a[2]), "r"(a[3]), "r"(b[0]), "r"(b[1]));
}
__device__ __forceinline__ void ldsm4(uint32_t* r, uint32_t addr) {
    asm volatile("ldmatrix.sync.aligned.m8n8.x4.shared.b16 {%0,%1,%2,%3}, [%4];"
        : "=r"(r[0]), "=r"(r[1]), "=r"(r[2]), "=r"(r[3]) : "r"(addr));
}
__device__ __forceinline__ void ldsm4t(uint32_t* r, uint32_t addr) {
    asm volatile("ldmatrix.sync.aligned.m8n8.x4.trans.shared.b16 {%0,%1,%2,%3}, [%4];"
        : "=r"(r[0]), "=r"(r[1]), "=r"(r[2]), "=r"(r[3]) : "r"(addr));
}
__device__ __forceinline__ void split_bf(float v, __nv_bfloat16& h, __nv_bfloat16& l) {
    h = __float2bfloat16(v);
    l = __float2bfloat16(v - __bfloat162float(h));
}
__device__ __forceinline__ uint32_t pk(__nv_bfloat16 a, __nv_bfloat16 b) {
    return (uint32_t)__bfloat16_as_ushort(a) | ((uint32_t)__bfloat16_as_ushort(b) << 16);
}

// ---------------------------------------------------------------------------
// Setup: build hi/lo pad-72 images of [Wq|Wk*0.125|Wv] and E.
// ---------------------------------------------------------------------------
__global__ __launch_bounds__(256) void setup_kernel(
    const float* __restrict__ Wk, const float* __restrict__ Wq,
    const float* __restrict__ Wv, const float* __restrict__ E)
{
    int id = blockIdx.x * 256 + threadIdx.x;
    if (id < 4 * 192 * 72) {
        int kt = id / (192 * 72);
        int rem = id % (192 * 72);
        int n = rem / 72, k = rem % 72;
        float v = 0.f;
        if (k < 64) {
            int which = n >> 6, col = n & 63;
            const float* W = (which == 0) ? Wq : (which == 1) ? Wk : Wv;
            v = W[(kt * 64 + k) * Hn + col];
            if (which == 1) v *= 0.125f;
        }
        __nv_bfloat16 h, l;
        split_bf(v, h, l);
        g_Wh[id] = h;
        g_Wl[id] = l;
    } else {
        int id2 = id - 4 * 192 * 72;
        if (id2 < 256 * 72) {
            int d = id2 / 72, k = id2 % 72;
            float v = (k < 64) ? E[d * Hn + k] : 0.f;
            __nv_bfloat16 h, l;
            split_bf(v, h, l);
            g_Eh[id2] = h;
            g_El[id2] = l;
        }
    }
}

// ---------------------------------------------------------------------------
// Fused qkv GEMM (bf16x3, ldmatrix). grid=512, block=512.
// B-image copy issued BEFORE A-split so B LDG latency hides under split ALU.
// ---------------------------------------------------------------------------
__global__ __launch_bounds__(512, 1) void qkv_kernel(const float* __restrict__ x)
{
    extern __shared__ __nv_bfloat16 smb[];
    __nv_bfloat16* Ah = smb;
    __nv_bfloat16* Al = Ah + 128 * 72;
    __nv_bfloat16* Bh = Al + 128 * 72;
    __nv_bfloat16* Bl = Bh + 192 * 72;

    const int row0 = blockIdx.x * 128;
    const int tid = threadIdx.x, w = tid >> 5, lane = tid & 31;
    const int wm = w >> 2, wn = w & 3;
    const int g = lane >> 2, l2 = lane & 3;

    const uint32_t aH = smem_u32(Ah), aL = smem_u32(Al);
    const uint32_t bH = smem_u32(Bh), bL = smem_u32(Bl);
    const int arow = wm * 32 + (lane & 15);
    const int acol = (lane >> 4) * 8;
    const int brow = wn * 48 + (lane & 7) + (lane >> 4) * 8;
    const int bcol = ((lane >> 3) & 1) * 8;

    float acc[2][6][4] = {};

    for (int ct = 0; ct < 4; ct++) {
        float4 xv[4];
        #pragma unroll
        for (int i = 0; i < 4; i++) {
            int f = tid + i * 512;
            int r = f >> 4, c4 = (f & 15) << 2;
            xv[i] = *(const float4*)(x + (row0 + r) * Cn + ct * 64 + c4);
        }
        __syncthreads();   // prior chunk's ldmatrix reads done

        // B copy FIRST: independent LDGs issue, latency overlaps A-split ALU
        {
            uint4* dh = (uint4*)Bh;
            uint4* dl = (uint4*)Bl;
            const uint4* sh = (const uint4*)(g_Wh + ct * 192 * 72);
            const uint4* sl = (const uint4*)(g_Wl + ct * 192 * 72);
            #pragma unroll
            for (int idx = tid; idx < 1728; idx += 512) {
                dh[idx] = sh[idx];
                dl[idx] = sl[idx];
            }
        }
        #pragma unroll
        for (int i = 0; i < 4; i++) {
            int f = tid + i * 512;
            int r = f >> 4, c4 = (f & 15) << 2;
            __nv_bfloat16 h0, l0, h1, l1, h2, l2b, h3, l3;
            split_bf(xv[i].x, h0, l0);
            split_bf(xv[i].y, h1, l1);
            split_bf(xv[i].z, h2, l2b);
            split_bf(xv[i].w, h3, l3);
            uint2 uh = {pk(h0, h1), pk(h2, h3)};
            uint2 ul = {pk(l0, l1), pk(l2b, l3)};
            *(uint2*)(Ah + r * 72 + c4) = uh;
            *(uint2*)(Al + r * 72 + c4) = ul;
        }
        __syncthreads();

        #pragma unroll
        for (int ks = 0; ks < 64; ks += 16) {
            uint32_t ah[2][4], al[2][4], bh[3][4], bl[3][4];
            #pragma unroll
            for (int mi = 0; mi < 2; mi++) {
                uint32_t off = ((arow + mi * 16) * 72 + ks + acol) * 2;
                ldsm4(ah[mi], aH + off);
                ldsm4(al[mi], aL + off);
            }
            #pragma unroll
            for (int nj = 0; nj < 3; nj++) {
                uint32_t off = ((brow + nj * 16) * 72 + ks + bcol) * 2;
                ldsm4(bh[nj], bH + off);
                ldsm4(bl[nj], bL + off);
            }
            #pragma unroll
            for (int mi = 0; mi < 2; mi++)
                #pragma unroll
                for (int ni = 0; ni < 6; ni++) {
                    const uint32_t* ph = &bh[ni >> 1][(ni & 1) * 2];
                    const uint32_t* pl = &bl[ni >> 1][(ni & 1) * 2];
                    mma_bf16(acc[mi][ni], ah[mi], ph);
                    mma_bf16(acc[mi][ni], ah[mi], pl);
                    mma_bf16(acc[mi][ni], al[mi], ph);
                }
        }
    }

    #pragma unroll
    for (int mi = 0; mi < 2; mi++) {
        int rr = row0 + wm * 32 + mi * 16 + g;
        #pragma unroll
        for (int ni = 0; ni < 6; ni++) {
            int n = wn * 48 + ni * 8 + l2 * 2;
            __nv_bfloat16* dh = (n < 64) ? g_qh : (n < 128) ? g_kh : g_vh;
            __nv_bfloat16* dl = (n < 64) ? g_ql : (n < 128) ? g_kl : g_vl;
            int col = n & 63;
            __nv_bfloat16 h0, l0, h1, l1, h2, l2b, h3, l3;
            split_bf(acc[mi][ni][0], h0, l0);
            split_bf(acc[mi][ni][1], h1, l1);
            split_bf(acc[mi][ni][2], h2, l2b);
            split_bf(acc[mi][ni][3], h3, l3);
            *(uint32_t*)(dh + rr * 64 + col)       = pk(h0, h1);
            *(uint32_t*)(dl + rr * 64 + col)       = pk(l0, l1);
            *(uint32_t*)(dh + (rr + 8) * 64 + col) = pk(h2, h3);
            *(uint32_t*)(dl + (rr + 8) * 64 + col) = pk(l2b, l3);
        }
    }
}

// ---------------------------------------------------------------------------
// pos: P = q @ E^T (bf16x3, ldmatrix). grid=(1024,2), block=256.
// E copy (larger) issued first, then q copy. fp16 s-layout stores.
// ---------------------------------------------------------------------------
__global__ __launch_bounds__(256) void pos_kernel()
{
    const int row0  = blockIdx.x * 64;
    const int t0    = row0 & 255;
    const int nbase = blockIdx.y * 128;
    const int dmin  = 192 - t0;
    if (nbase + 127 < dmin) return;

    extern __shared__ __nv_bfloat16 smb[];
    __nv_bfloat16* Ah = smb;
    __nv_bfloat16* Al = Ah + 64 * 72;
    __nv_bfloat16* Eh = Al + 64 * 72;
    __nv_bfloat16* El = Eh + 128 * 72;
    float* stage = (float*)smb;       // reused after compute

    const int tid = threadIdx.x, w = tid >> 5, lane = tid & 31;
    const int wm = w >> 2, wn = w & 3;
    const int g = lane >> 2, l2 = lane & 3;

    {
        uint4* dh = (uint4*)Eh;
        uint4* dl = (uint4*)El;
        const uint4* sh = (const uint4*)(g_Eh + nbase * 72);
        const uint4* sl = (const uint4*)(g_El + nbase * 72);
        #pragma unroll
        for (int idx = tid; idx < 1152; idx += 256) {
            dh[idx] = sh[idx];
            dl[idx] = sl[idx];
        }
    }
    #pragma unroll
    for (int i = 0; i < 2; i++) {
        int f = tid + i * 256;
        int r = f >> 3, c = (f & 7) * 8;
        *(uint4*)(Ah + r * 72 + c) = *(const uint4*)(g_qh + (row0 + r) * 64 + c);
        *(uint4*)(Al + r * 72 + c) = *(const uint4*)(g_ql + (row0 + r) * 64 + c);
    }
    __syncthreads();

    const bool live = (nbase + wn * 32 + 31 >= dmin);
    float acc[2][4][4] = {};
    if (live) {
        const uint32_t aH = smem_u32(Ah), aL = smem_u32(Al);
        const uint32_t bH = smem_u32(Eh), bL = smem_u32(El);
        const int arow = wm * 32 + (lane & 15);
        const int acol = (lane >> 4) * 8;
        const int brow = wn * 32 + (lane & 7) + (lane >> 4) * 8;
        const int bcol = ((lane >> 3) & 1) * 8;
        #pragma unroll
        for (int ks = 0; ks < 64; ks += 16) {
            uint32_t ah[2][4], al[2][4], bh[2][4], bl[2][4];
            #pragma unroll
            for (int mi = 0; mi < 2; mi++) {
                uint32_t off = ((arow + mi * 16) * 72 + ks + acol) * 2;
                ldsm4(ah[mi], aH + off);
                ldsm4(al[mi], aL + off);
            }
            #pragma unroll
            for (int nj = 0; nj < 2; nj++) {
                uint32_t off = ((brow + nj * 16) * 72 + ks + bcol) * 2;
                ldsm4(bh[nj], bH + off);
                ldsm4(bl[nj], bL + off);
            }
            #pragma unroll
            for (int mi = 0; mi < 2; mi++)
                #pragma unroll
                for (int ni = 0; ni < 4; ni++) {
                    const uint32_t* ph = &bh[ni >> 1][(ni & 1) * 2];
                    const uint32_t* pl = &bl[ni >> 1][(ni & 1) * 2];
                    mma_bf16(acc[mi][ni], ah[mi], ph);
                    mma_bf16(acc[mi][ni], ah[mi], pl);
                    mma_bf16(acc[mi][ni], al[mi], ph);
                }
        }
    }
    __syncthreads();

    if (live) {
        #pragma unroll
        for (int mi = 0; mi < 2; mi++) {
            int rl = wm * 32 + mi * 16 + g;
            #pragma unroll
            for (int ni = 0; ni < 4; ni++) {
                int dl = wn * 32 + ni * 8 + l2 * 2;
                stage[rl * 132 + dl]           = acc[mi][ni][0];
                stage[rl * 132 + dl + 1]       = acc[mi][ni][1];
                stage[(rl + 8) * 132 + dl]     = acc[mi][ni][2];
                stage[(rl + 8) * 132 + dl + 1] = acc[mi][ni][3];
            }
        }
    }
    __syncthreads();

    // aligned fp16 s-layout store: 4 threads per row
    {
        int r = tid >> 2, j = tid & 3;
        int t = (row0 + r) & 255;
        long grow = (long)(row0 + r) * 256;
        int slr = nbase + t - 255;
        int s_hi = slr + 128;
        if (s_hi > 0) {
            int s_lo = slr < 0 ? 0 : slr;
            int a0 = (s_lo + 7) & ~7;
            int a1;
            if (nbase == 128) {
                a1 = (s_hi + 7) & ~7;
                if (a1 > 256) a1 = 256;
            } else {
                a1 = s_hi & ~7;
            }
            const float* srow = stage + r * 132 - slr;
            for (int hs = s_lo + j; hs < a0 && hs < s_hi; hs += 4)
                g_ps[grow + hs] = __float2half(srow[hs]);
            for (int s8 = a0 + j * 8; s8 < a1; s8 += 32) {
                __half tmp[8];
                #pragma unroll
                for (int e = 0; e < 8; e++) tmp[e] = __float2half(srow[s8 + e]);
                *(uint4*)(g_ps + grow + s8) = *(const uint4*)tmp;
            }
            if (nbase == 0) {
                for (int ts = a1 + j; ts < s_hi; ts += 4)
                    g_ps[grow + ts] = __float2half(srow[ts]);
            }
        }
    }
}

// ---------------------------------------------------------------------------
// attention via bf16x3 mma (R13). grid=(256,4), block=512. Heavy tiles first.
// ---------------------------------------------------------------------------
__global__ __launch_bounds__(512, 1) void attn_kernel(float* __restrict__ out)
{
    extern __shared__ char smc[];
    float* sc = (float*)smc;                                   // 64*264 f32
    __nv_bfloat16* wh = (__nv_bfloat16*)(smc + 64 * 264 * 4);  // 64*264
    __nv_bfloat16* wl = wh + 64 * 264;
    __nv_bfloat16* qh = wl + 64 * 264;                         // 64*72
    __nv_bfloat16* ql = qh + 64 * 72;
    __nv_bfloat16* kh = ql + 64 * 72;                          // 256*72
    __nv_bfloat16* kl = kh + 256 * 72;

    const int b  = blockIdx.x;
    const int tt = 3 - blockIdx.y;          // heavy first
    const int t0 = tt * 64;
    const int nst = tt + 1;
    const int send = nst * 64;
    const int tid = threadIdx.x, w = tid >> 5, lane = tid & 31;
    const int g = lane >> 2, l2 = lane & 3;

    const uint32_t qHa = smem_u32(qh), qLa = smem_u32(ql);
    const uint32_t kHa = smem_u32(kh), kLa = smem_u32(kl);
    const uint32_t wHa = smem_u32(wh), wLa = smem_u32(wl);

    // ---- phase A: pure copies + aligned fp16 P prefill ----
    {
        int r = tid >> 3, c = (tid & 7) * 8;
        *(uint4*)(qh + r * 72 + c) = *(const uint4*)(g_qh + ((long)(b * Tn + t0 + r)) * 64 + c);
        *(uint4*)(ql + r * 72 + c) = *(const uint4*)(g_ql + ((long)(b * Tn + t0 + r)) * 64 + c);
    }
    for (int f = tid; f < send * 8; f += 512) {
        int r = f >> 3, c = (f & 7) * 8;
        *(uint4*)(kh + r * 72 + c) = *(const uint4*)(g_kh + ((long)(b * Tn + r)) * 64 + c);
        *(uint4*)(kl + r * 72 + c) = *(const uint4*)(g_kl + ((long)(b * Tn + r)) * 64 + c);
    }
    #pragma unroll
    for (int i = 0; i < 4; i++) {
        int f = tid + i * 512;
        int r = f >> 5, s8 = (f & 31) << 3;
        if (s8 < send) {
            int t = t0 + r;
            uint4 pv = *(const uint4*)(g_ps + ((long)(b * Tn + t)) * 256 + s8);
            const __half* ph = (const __half*)&pv;
            float o[8];
            #pragma unroll
            for (int e = 0; e < 8; e++)
                o[e] = (s8 + e <= t) ? __half2float(ph[e]) : -1e30f;
            *(float4*)&sc[r * 264 + s8]     = make_float4(o[0], o[1], o[2], o[3]);
            *(float4*)&sc[r * 264 + s8 + 4] = make_float4(o[4], o[5], o[6], o[7]);
        }
    }
    __syncthreads();

    // ---- score phase: warps 2m x 8n, one 32x32 tile each ----
    {
        const int wm = w >> 3, wn = w & 7;
        const int cb = wn * 32;
        if (cb < send && cb <= t0 + wm * 32 + 31) {
            const int arow = wm * 32 + (lane & 15);
            const int acol = (lane >> 4) * 8;
            const int brow = cb + (lane & 7) + (lane >> 4) * 8;
            const int bcol = ((lane >> 3) & 1) * 8;
            float acc[2][4][4] = {};
            #pragma unroll
            for (int ks = 0; ks < 4; ks++) {
                uint32_t ah[2][4], al[2][4], bh[2][4], bl[2][4];
                #pragma unroll
                for (int mi = 0; mi < 2; mi++) {
                    uint32_t off = ((arow + mi * 16) * 72 + ks * 16 + acol) * 2;
                    ldsm4(ah[mi], qHa + off);
                    ldsm4(al[mi], qLa + off);
                }
                #pragma unroll
                for (int nj = 0; nj < 2; nj++) {
                    uint32_t off = ((brow + nj * 16) * 72 + ks * 16 + bcol) * 2;
                    ldsm4(bh[nj], kHa + off);
                    ldsm4(bl[nj], kLa + off);
                }
                #pragma unroll
                for (int mi = 0; mi < 2; mi++)
                    #pragma unroll
                    for (int ni = 0; ni < 4; ni++) {
                        const uint32_t* ph = &bh[ni >> 1][(ni & 1) * 2];
                        const uint32_t* pl = &bl[ni >> 1][(ni & 1) * 2];
                        mma_bf16(acc[mi][ni], ah[mi], ph);
                        mma_bf16(acc[mi][ni], ah[mi], pl);
                        mma_bf16(acc[mi][ni], al[mi], ph);
                    }
            }
            #pragma unroll
            for (int mi = 0; mi < 2; mi++)
                #pragma unroll
                for (int ni = 0; ni < 4; ni++) {
                    int rloc = wm * 32 + mi * 16 + g;
                    int sbase = cb + ni * 8 + l2 * 2;
                    #pragma unroll
                    for (int hf = 0; hf < 2; hf++) {
                        int row = rloc + hf * 8;
                        float2 cur = *(float2*)&sc[row * 264 + sbase];
                        cur.x += acc[mi][ni][hf * 2];
                        cur.y += acc[mi][ni][hf * 2 + 1];
                        *(float2*)&sc[row * 264 + sbase] = cur;
                    }
                }
        }
    }
    __syncthreads();

    // ---- load live v rows into kh/kl ----
    for (int f = tid; f < send * 8; f += 512) {
        int r = f >> 3, c = (f & 7) * 8;
        *(uint4*)(kh + r * 72 + c) = *(const uint4*)(g_vh + ((long)(b * Tn + r)) * 64 + c);
        *(uint4*)(kl + r * 72 + c) = *(const uint4*)(g_vl + ((long)(b * Tn + r)) * 64 + c);
    }

    // ---- softmax: 16 warps x 4 rows, bf16 hi/lo weight emit ----
    for (int r = w * 4; r < w * 4 + 4; r++) {
        float m = -1e30f;
        for (int i = 0; i < nst; i++) {
            float2 v = *(const float2*)&sc[r * 264 + i * 64 + lane * 2];
            m = fmaxf(m, fmaxf(v.x, v.y));
        }
        #pragma unroll
        for (int o = 16; o; o >>= 1) m = fmaxf(m, __shfl_xor_sync(0xffffffffu, m, o));
        float sum = 0.f;
        for (int i = 0; i < nst; i++) {
            float2 v = *(const float2*)&sc[r * 264 + i * 64 + lane * 2];
            v.x = __expf(v.x - m);
            v.y = __expf(v.y - m);
            sum += v.x + v.y;
            *(float2*)&sc[r * 264 + i * 64 + lane * 2] = v;
        }
        #pragma unroll
        for (int o = 16; o; o >>= 1) sum += __shfl_xor_sync(0xffffffffu, sum, o);
        float inv = 1.0f / sum;
        for (int i = 0; i < nst; i++) {
            float2 e = *(const float2*)&sc[r * 264 + i * 64 + lane * 2];
            float w0 = e.x * inv, w1 = e.y * inv;
            __nv_bfloat16 h0, l0, h1, l1;
            split_bf(w0, h0, l0);
            split_bf(w1, h1, l1);
            *(uint32_t*)&wh[r * 264 + i * 64 + lane * 2] = pk(h0, h1);
            *(uint32_t*)&wl[r * 264 + i * 64 + lane * 2] = pk(l0, l1);
        }
    }
    __syncthreads();

    // ---- out = wei @ v : split-K over warps (2m x 2n x 4k) ----
    {
        const int wk = w & 3;
        const int wn2 = (w >> 2) & 1;
        const int wm2 = w >> 3;
        if (wk < nst) {
            const int arow = wm2 * 32 + (lane & 15);
            const int acol = (lane >> 4) * 8;
            const int vrow = (lane & 7) + ((lane >> 3) & 1) * 8;
            const int vcol = wn2 * 32 + (lane >> 4) * 8;
            float oacc[2][4][4] = {};
            #pragma unroll
            for (int ks = 0; ks < 4; ks++) {
                uint32_t aw[2][4], awl[2][4], bvh[2][4], bvl[2][4];
                #pragma unroll
                for (int mi = 0; mi < 2; mi++) {
                    uint32_t aoff = ((arow + mi * 16) * 264 + wk * 64 + ks * 16 + acol) * 2;
                    ldsm4(aw[mi],  wHa + aoff);
                    ldsm4(awl[mi], wLa + aoff);
                }
                #pragma unroll
                for (int nj = 0; nj < 2; nj++) {
                    uint32_t voff = ((wk * 64 + ks * 16 + vrow) * 72 + vcol + nj * 16) * 2;
                    ldsm4t(bvh[nj], kHa + voff);
                    ldsm4t(bvl[nj], kLa + voff);
                }
                #pragma unroll
                for (int mi = 0; mi < 2; mi++)
                    #pragma unroll
                    for (int ni = 0; ni < 4; ni++) {
                        const uint32_t* ph = &bvh[ni >> 1][(ni & 1) * 2];
                        const uint32_t* pl = &bvl[ni >> 1][(ni & 1) * 2];
                        mma_bf16(oacc[mi][ni], aw[mi],  ph);
                        mma_bf16(oacc[mi][ni], aw[mi],  pl);
                        mma_bf16(oacc[mi][ni], awl[mi], ph);
                    }
            }
            float* slice = sc + wk * 4096;
            #pragma unroll
            for (int mi = 0; mi < 2; mi++)
                #pragma unroll
                for (int ni = 0; ni < 4; ni++) {
                    int row = wm2 * 32 + mi * 16 + g;
                    int col = wn2 * 32 + ni * 8 + l2 * 2;
                    float2 o0 = {oacc[mi][ni][0], oacc[mi][ni][1]};
                    float2 o1 = {oacc[mi][ni][2], oacc[mi][ni][3]};
                    *(float2*)&slice[row * 64 + col] = o0;
                    *(float2*)&slice[(row + 8) * 64 + col] = o1;
                }
        }
    }
    __syncthreads();

    // ---- reduce nst slices and store ----
    #pragma unroll
    for (int i = 0; i < 8; i++) {
        int idx = tid + i * 512;
        float s = sc[idx];
        for (int j = 1; j < nst; j++) s += sc[j * 4096 + idx];
        int row = idx >> 6, col = idx & 63;
        out[((long)(b * Tn + t0 + row)) * Hn + col] = s;
    }
}

// ---------------------------------------------------------------------------
extern "C" void kernel_launch(void* const* d_in, const int* in_sizes, int n_in,
                              void* d_out, int out_size)
{
    const float* x  = (const float*)d_in[0];
    const float* Wk = (const float*)d_in[1];
    const float* Wq = (const float*)d_in[2];
    const float* Wv = (const float*)d_in[3];
    const float* E  = (const float*)d_in[4];
    float* out = (float*)d_out;

    setup_kernel<<<288, 256>>>(Wk, Wq, Wv, E);

    const int qkv_sm = (2 * 128 * 72 + 2 * 192 * 72) * (int)sizeof(__nv_bfloat16); // 92160
    cudaFuncSetAttribute(qkv_kernel, cudaFuncAttributeMaxDynamicSharedMemorySize, qkv_sm);
    qkv_kernel<<<Bn * Tn / 128, 512, qkv_sm>>>(x);

    const int pos_sm = (2 * 64 * 72 + 2 * 128 * 72) * (int)sizeof(__nv_bfloat16);  // 55296
    cudaFuncSetAttribute(pos_kernel, cudaFuncAttributeMaxDynamicSharedMemorySize, pos_sm);
    pos_kernel<<<dim3(Bn * Tn / 64, 2), 256, pos_sm>>>();

    const int attn_sm = 64 * 264 * 4 + 2 * 64 * 264 * 2 + 2 * 64 * 72 * 2
                      + 2 * 256 * 72 * 2;                                          // 227328
    cudaFuncSetAttribute(attn_kernel, cudaFuncAttributeMaxDynamicSharedMemorySize, attn_sm);
    attn_kernel<<<dim3(Bn, Tn / 64), 512, attn_sm>>>(out);
}

// round 16
// speedup vs baseline: 1.4907x; 1.0917x over previous
#include <cuda_runtime.h>
#include <cuda_bf16.h>
#include <cstdint>

#define Bn 256
#define Tn 256
#define Cn 256
#define Hn 64

// ---------------- scratch ----------------
__device__ __align__(16) __nv_bfloat16 g_qh[Bn*Tn*Hn];
__device__ __align__(16) __nv_bfloat16 g_ql[Bn*Tn*Hn];
__device__ __align__(16) __nv_bfloat16 g_kh[Bn*Tn*Hn];
__device__ __align__(16) __nv_bfloat16 g_kl[Bn*Tn*Hn];
__device__ __align__(16) __nv_bfloat16 g_vh[Bn*Tn*Hn];
__device__ __align__(16) __nv_bfloat16 g_vl[Bn*Tn*Hn];
__device__ __align__(16) __nv_bfloat16 g_Wh[4*192*72];
__device__ __align__(16) __nv_bfloat16 g_Wl[4*192*72];
__device__ __align__(16) __nv_bfloat16 g_Eh[256*72];
__device__ __align__(16) __nv_bfloat16 g_El[256*72];

// ---------------- helpers ----------------
__device__ __forceinline__ uint32_t smem_u32(const void* p) {
    uint32_t a;
    asm("{ .reg .u64 t; cvta.to.shared.u64 t, %1; cvt.u32.u64 %0, t; }" : "=r"(a) : "l"(p));
    return a;
}
__device__ __forceinline__ void mma_bf16(float* c, const uint32_t* a, const uint32_t* b) {
    asm volatile(
        "mma.sync.aligned.m16n8k16.row.col.f32.bf16.bf16.f32 "
        "{%0,%1,%2,%3}, {%4,%5,%6,%7}, {%8,%9}, {%0,%1,%2,%3};"
        : "+f"(c[0]), "+f"(c[1]), "+f"(c[2]), "+f"(c[3])
        : "r"(a[0]), "r"(a[1]), "r"(a[2]), "r"(a[3]), "r"(b[0]), "r"(b[1]));
}
__device__ __forceinline__ void ldsm4(uint32_t* r, uint32_t addr) {
    asm volatile("ldmatrix.sync.aligned.m8n8.x4.shared.b16 {%0,%1,%2,%3}, [%4];"
        : "=r"(r[0]), "=r"(r[1]), "=r"(r[2]), "=r"(r[3]) : "r"(addr));
}
__device__ __forceinline__ void ldsm4t(uint32_t* r, uint32_t addr) {
    asm volatile("ldmatrix.sync.aligned.m8n8.x4.trans.shared.b16 {%0,%1,%2,%3}, [%4];"
        : "=r"(r[0]), "=r"(r[1]), "=r"(r[2]), "=r"(r[3]) : "r"(addr));
}
__device__ __forceinline__ void split_bf(float v, __nv_bfloat16& h, __nv_bfloat16& l) {
    h = __float2bfloat16(v);
    l = __float2bfloat16(v - __bfloat162float(h));
}
__device__ __forceinline__ uint32_t pk(__nv_bfloat16 a, __nv_bfloat16 b) {
    return (uint32_t)__bfloat16_as_ushort(a) | ((uint32_t)__bfloat16_as_ushort(b) << 16);
}

// ---------------------------------------------------------------------------
// Setup: build hi/lo pad-72 images of [Wq|Wk*0.125|Wv] and E.
// ---------------------------------------------------------------------------
__global__ __launch_bounds__(256) void setup_kernel(
    const float* __restrict__ Wk, const float* __restrict__ Wq,
    const float* __restrict__ Wv, const float* __restrict__ E)
{
    int id = blockIdx.x * 256 + threadIdx.x;
    if (id < 4 * 192 * 72) {
        int kt = id / (192 * 72);
        int rem = id % (192 * 72);
        int n = rem / 72, k = rem % 72;
        float v = 0.f;
        if (k < 64) {
            int which = n >> 6, col = n & 63;
            const float* W = (which == 0) ? Wq : (which == 1) ? Wk : Wv;
            v = W[(kt * 64 + k) * Hn + col];
            if (which == 1) v *= 0.125f;
        }
        __nv_bfloat16 h, l;
        split_bf(v, h, l);
        g_Wh[id] = h;
        g_Wl[id] = l;
    } else {
        int id2 = id - 4 * 192 * 72;
        if (id2 < 256 * 72) {
            int d = id2 / 72, k = id2 % 72;
            float v = (k < 64) ? E[d * Hn + k] : 0.f;
            __nv_bfloat16 h, l;
            split_bf(v, h, l);
            g_Eh[id2] = h;
            g_El[id2] = l;
        }
    }
}

// ---------------------------------------------------------------------------
// Fused qkv GEMM (bf16x3, ldmatrix). grid=512, block=512. (unchanged R15)
// ---------------------------------------------------------------------------
__global__ __launch_bounds__(512, 1) void qkv_kernel(const float* __restrict__ x)
{
    extern __shared__ __nv_bfloat16 smb[];
    __nv_bfloat16* Ah = smb;
    __nv_bfloat16* Al = Ah + 128 * 72;
    __nv_bfloat16* Bh = Al + 128 * 72;
    __nv_bfloat16* Bl = Bh + 192 * 72;

    const int row0 = blockIdx.x * 128;
    const int tid = threadIdx.x, w = tid >> 5, lane = tid & 31;
    const int wm = w >> 2, wn = w & 3;
    const int g = lane >> 2, l2 = lane & 3;

    const uint32_t aH = smem_u32(Ah), aL = smem_u32(Al);
    const uint32_t bH = smem_u32(Bh), bL = smem_u32(Bl);
    const int arow = wm * 32 + (lane & 15);
    const int acol = (lane >> 4) * 8;
    const int brow = wn * 48 + (lane & 7) + (lane >> 4) * 8;
    const int bcol = ((lane >> 3) & 1) * 8;

    float acc[2][6][4] = {};

    for (int ct = 0; ct < 4; ct++) {
        float4 xv[4];
        #pragma unroll
        for (int i = 0; i < 4; i++) {
            int f = tid + i * 512;
            int r = f >> 4, c4 = (f & 15) << 2;
            xv[i] = *(const float4*)(x + (row0 + r) * Cn + ct * 64 + c4);
        }
        __syncthreads();

        {
            uint4* dh = (uint4*)Bh;
            uint4* dl = (uint4*)Bl;
            const uint4* sh = (const uint4*)(g_Wh + ct * 192 * 72);
            const uint4* sl = (const uint4*)(g_Wl + ct * 192 * 72);
            #pragma unroll
            for (int idx = tid; idx < 1728; idx += 512) {
                dh[idx] = sh[idx];
                dl[idx] = sl[idx];
            }
        }
        #pragma unroll
        for (int i = 0; i < 4; i++) {
            int f = tid + i * 512;
            int r = f >> 4, c4 = (f & 15) << 2;
            __nv_bfloat16 h0, l0, h1, l1, h2, l2b, h3, l3;
            split_bf(xv[i].x, h0, l0);
            split_bf(xv[i].y, h1, l1);
            split_bf(xv[i].z, h2, l2b);
            split_bf(xv[i].w, h3, l3);
            uint2 uh = {pk(h0, h1), pk(h2, h3)};
            uint2 ul = {pk(l0, l1), pk(l2b, l3)};
            *(uint2*)(Ah + r * 72 + c4) = uh;
            *(uint2*)(Al + r * 72 + c4) = ul;
        }
        __syncthreads();

        #pragma unroll
        for (int ks = 0; ks < 64; ks += 16) {
            uint32_t ah[2][4], al[2][4], bh[3][4], bl[3][4];
            #pragma unroll
            for (int mi = 0; mi < 2; mi++) {
                uint32_t off = ((arow + mi * 16) * 72 + ks + acol) * 2;
                ldsm4(ah[mi], aH + off);
                ldsm4(al[mi], aL + off);
            }
            #pragma unroll
            for (int nj = 0; nj < 3; nj++) {
                uint32_t off = ((brow + nj * 16) * 72 + ks + bcol) * 2;
                ldsm4(bh[nj], bH + off);
                ldsm4(bl[nj], bL + off);
            }
            #pragma unroll
            for (int mi = 0; mi < 2; mi++)
                #pragma unroll
                for (int ni = 0; ni < 6; ni++) {
                    const uint32_t* ph = &bh[ni >> 1][(ni & 1) * 2];
                    const uint32_t* pl = &bl[ni >> 1][(ni & 1) * 2];
                    mma_bf16(acc[mi][ni], ah[mi], ph);
                    mma_bf16(acc[mi][ni], ah[mi], pl);
                    mma_bf16(acc[mi][ni], al[mi], ph);
                }
        }
    }

    #pragma unroll
    for (int mi = 0; mi < 2; mi++) {
        int rr = row0 + wm * 32 + mi * 16 + g;
        #pragma unroll
        for (int ni = 0; ni < 6; ni++) {
            int n = wn * 48 + ni * 8 + l2 * 2;
            __nv_bfloat16* dh = (n < 64) ? g_qh : (n < 128) ? g_kh : g_vh;
            __nv_bfloat16* dl = (n < 64) ? g_ql : (n < 128) ? g_kl : g_vl;
            int col = n & 63;
            __nv_bfloat16 h0, l0, h1, l1, h2, l2b, h3, l3;
            split_bf(acc[mi][ni][0], h0, l0);
            split_bf(acc[mi][ni][1], h1, l1);
            split_bf(acc[mi][ni][2], h2, l2b);
            split_bf(acc[mi][ni][3], h3, l3);
            *(uint32_t*)(dh + rr * 64 + col)       = pk(h0, h1);
            *(uint32_t*)(dl + rr * 64 + col)       = pk(l0, l1);
            *(uint32_t*)(dh + (rr + 8) * 64 + col) = pk(h2, h3);
            *(uint32_t*)(dl + (rr + 8) * 64 + col) = pk(l2b, l3);
        }
    }
}

// ---------------------------------------------------------------------------
// attention with FUSED position term. grid=(256,4), block=512.
// Phase A0: q/k copies, E half0 into wh/wl, sc init -1e30.
// Phase P:  P = q @ E^T per <=128-wide d-half, scalar-scatter into sc
//           (s = 128*half + dloc + row - 63); unstored entries stay masked.
// Then: score RMW, softmax (overwrites wh/wl), PV split-K. No g_ps.
// ---------------------------------------------------------------------------
__global__ __launch_bounds__(512, 1) void attn_kernel(float* __restrict__ out)
{
    extern __shared__ char smc[];
    float* sc = (float*)smc;                                   // 64*264 f32
    __nv_bfloat16* wh = (__nv_bfloat16*)(smc + 64 * 264 * 4);  // 64*264
    __nv_bfloat16* wl = wh + 64 * 264;
    __nv_bfloat16* qh = wl + 64 * 264;                         // 64*72
    __nv_bfloat16* ql = qh + 64 * 72;
    __nv_bfloat16* kh = ql + 64 * 72;                          // 256*72
    __nv_bfloat16* kl = kh + 256 * 72;

    const int b  = blockIdx.x;
    const int tt = 3 - blockIdx.y;          // heavy first
    const int t0 = tt * 64;
    const int nst = tt + 1;
    const int send = nst * 64;
    const int dlo = 192 - t0;
    const int tid = threadIdx.x, w = tid >> 5, lane = tid & 31;
    const int g = lane >> 2, l2 = lane & 3;

    const uint32_t qHa = smem_u32(qh), qLa = smem_u32(ql);
    const uint32_t kHa = smem_u32(kh), kLa = smem_u32(kl);
    const uint32_t wHa = smem_u32(wh), wLa = smem_u32(wl);

    // ---- phase A0: q/k copies + E half0 + sc init ----
    {
        int r = tid >> 3, c = (tid & 7) * 8;
        *(uint4*)(qh + r * 72 + c) = *(const uint4*)(g_qh + ((long)(b * Tn + t0 + r)) * 64 + c);
        *(uint4*)(ql + r * 72 + c) = *(const uint4*)(g_ql + ((long)(b * Tn + t0 + r)) * 64 + c);
    }
    for (int f = tid; f < send * 8; f += 512) {
        int r = f >> 3, c = (f & 7) * 8;
        *(uint4*)(kh + r * 72 + c) = *(const uint4*)(g_kh + ((long)(b * Tn + r)) * 64 + c);
        *(uint4*)(kl + r * 72 + c) = *(const uint4*)(g_kl + ((long)(b * Tn + r)) * 64 + c);
    }
    {
        int rows0 = send < 128 ? send : 128;
        for (int f = tid; f < rows0 * 8; f += 512) {
            int r = f >> 3, c = (f & 7) * 8;
            *(uint4*)(wh + r * 72 + c) = *(const uint4*)(g_Eh + (dlo + r) * 72 + c);
            *(uint4*)(wl + r * 72 + c) = *(const uint4*)(g_El + (dlo + r) * 72 + c);
        }
    }
    {
        const float4 neg = make_float4(-1e30f, -1e30f, -1e30f, -1e30f);
        #pragma unroll
        for (int i = 0; i < 8; i++) {
            int f = tid + i * 512;
            int r = f >> 6, s4 = (f & 63) << 2;
            *(float4*)&sc[r * 264 + s4] = neg;
        }
    }
    __syncthreads();

    // ---- phase P: position GEMM per d-half, scatter into sc ----
    {
        const int wm = w >> 3, wn = w & 7;
        const int nhalf = (send + 127) >> 7;
        for (int hh = 0; hh < nhalf; hh++) {
            if (hh == 1) {
                __syncthreads();   // half0 E reads done
                for (int f = tid; f < (send - 128) * 8; f += 512) {
                    int r = f >> 3, c = (f & 7) * 8;
                    *(uint4*)(wh + r * 72 + c) = *(const uint4*)(g_Eh + (dlo + 128 + r) * 72 + c);
                    *(uint4*)(wl + r * 72 + c) = *(const uint4*)(g_El + (dlo + 128 + r) * 72 + c);
                }
                __syncthreads();
            }
            int wcap = send - hh * 128;
            if (wcap > 128) wcap = 128;
            const int cb = wn * 16;
            // skip tiles fully outside [0,wcap) or mapping entirely to s < 0
            if (cb < wcap && !(hh == 0 && cb + wm * 32 < 17)) {
                const int arow = wm * 32 + (lane & 15);
                const int acol = (lane >> 4) * 8;
                const int brow = cb + (lane & 7) + (lane >> 4) * 8;
                const int bcol = ((lane >> 3) & 1) * 8;
                float pacc[2][2][4] = {};
                #pragma unroll
                for (int ks = 0; ks < 4; ks++) {
                    uint32_t ah[2][4], al[2][4], bh[4], bl[4];
                    #pragma unroll
                    for (int mi = 0; mi < 2; mi++) {
                        uint32_t off = ((arow + mi * 16) * 72 + ks * 16 + acol) * 2;
                        ldsm4(ah[mi], qHa + off);
                        ldsm4(al[mi], qLa + off);
                    }
                    {
                        uint32_t off = (brow * 72 + ks * 16 + bcol) * 2;
                        ldsm4(bh, wHa + off);
                        ldsm4(bl, wLa + off);
                    }
                    #pragma unroll
                    for (int mi = 0; mi < 2; mi++)
                        #pragma unroll
                        for (int ni = 0; ni < 2; ni++) {
                            mma_bf16(pacc[mi][ni], ah[mi], &bh[ni * 2]);
                            mma_bf16(pacc[mi][ni], ah[mi], &bl[ni * 2]);
                            mma_bf16(pacc[mi][ni], al[mi], &bh[ni * 2]);
                        }
                }
                #pragma unroll
                for (int mi = 0; mi < 2; mi++)
                    #pragma unroll
                    for (int ni = 0; ni < 2; ni++)
                        #pragma unroll
                        for (int hf = 0; hf < 2; hf++) {
                            int row = wm * 32 + mi * 16 + g + hf * 8;
                            int s = hh * 128 + cb + ni * 8 + l2 * 2 + row - 63;
                            if (s >= 0)     sc[row * 264 + s]     = pacc[mi][ni][hf * 2];
                            if (s + 1 >= 0) sc[row * 264 + s + 1] = pacc[mi][ni][hf * 2 + 1];
                        }
            }
        }
    }
    __syncthreads();

    // ---- score phase: warps 2m x 8n, one 32x32 tile each, RMW into sc ----
    {
        const int wm = w >> 3, wn = w & 7;
        const int cb = wn * 32;
        if (cb < send && cb <= t0 + wm * 32 + 31) {
            const int arow = wm * 32 + (lane & 15);
            const int acol = (lane >> 4) * 8;
            const int brow = cb + (lane & 7) + (lane >> 4) * 8;
            const int bcol = ((lane >> 3) & 1) * 8;
            float acc[2][4][4] = {};
            #pragma unroll
            for (int ks = 0; ks < 4; ks++) {
                uint32_t ah[2][4], al[2][4], bh[2][4], bl[2][4];
                #pragma unroll
                for (int mi = 0; mi < 2; mi++) {
                    uint32_t off = ((arow + mi * 16) * 72 + ks * 16 + acol) * 2;
                    ldsm4(ah[mi], qHa + off);
                    ldsm4(al[mi], qLa + off);
                }
                #pragma unroll
                for (int nj = 0; nj < 2; nj++) {
                    uint32_t off = ((brow + nj * 16) * 72 + ks * 16 + bcol) * 2;
                    ldsm4(bh[nj], kHa + off);
                    ldsm4(bl[nj], kLa + off);
                }
                #pragma unroll
                for (int mi = 0; mi < 2; mi++)
                    #pragma unroll
                    for (int ni = 0; ni < 4; ni++) {
                        const uint32_t* ph = &bh[ni >> 1][(ni & 1) * 2];
                        const uint32_t* pl = &bl[ni >> 1][(ni & 1) * 2];
                        mma_bf16(acc[mi][ni], ah[mi], ph);
                        mma_bf16(acc[mi][ni], ah[mi], pl);
                        mma_bf16(acc[mi][ni], al[mi], ph);
                    }
            }
            #pragma unroll
            for (int mi = 0; mi < 2; mi++)
                #pragma unroll
                for (int ni = 0; ni < 4; ni++) {
                    int rloc = wm * 32 + mi * 16 + g;
                    int sbase = cb + ni * 8 + l2 * 2;
                    #pragma unroll
                    for (int hf = 0; hf < 2; hf++) {
                        int row = rloc + hf * 8;
                        float2 cur = *(float2*)&sc[row * 264 + sbase];
                        cur.x += acc[mi][ni][hf * 2];
                        cur.y += acc[mi][ni][hf * 2 + 1];
                        *(float2*)&sc[row * 264 + sbase] = cur;
                    }
                }
        }
    }
    __syncthreads();

    // ---- load live v rows into kh/kl ----
    for (int f = tid; f < send * 8; f += 512) {
        int r = f >> 3, c = (f & 7) * 8;
        *(uint4*)(kh + r * 72 + c) = *(const uint4*)(g_vh + ((long)(b * Tn + r)) * 64 + c);
        *(uint4*)(kl + r * 72 + c) = *(const uint4*)(g_vl + ((long)(b * Tn + r)) * 64 + c);
    }

    // ---- softmax: 16 warps x 4 rows, bf16 hi/lo weight emit ----
    for (int r = w * 4; r < w * 4 + 4; r++) {
        float m = -1e30f;
        for (int i = 0; i < nst; i++) {
            float2 v = *(const float2*)&sc[r * 264 + i * 64 + lane * 2];
            m = fmaxf(m, fmaxf(v.x, v.y));
        }
        #pragma unroll
        for (int o = 16; o; o >>= 1) m = fmaxf(m, __shfl_xor_sync(0xffffffffu, m, o));
        float sum = 0.f;
        for (int i = 0; i < nst; i++) {
            float2 v = *(const float2*)&sc[r * 264 + i * 64 + lane * 2];
            v.x = __expf(v.x - m);
            v.y = __expf(v.y - m);
            sum += v.x + v.y;
            *(float2*)&sc[r * 264 + i * 64 + lane * 2] = v;
        }
        #pragma unroll
        for (int o = 16; o; o >>= 1) sum += __shfl_xor_sync(0xffffffffu, sum, o);
        float inv = 1.0f / sum;
        for (int i = 0; i < nst; i++) {
            float2 e = *(const float2*)&sc[r * 264 + i * 64 + lane * 2];
            float w0 = e.x * inv, w1 = e.y * inv;
            __nv_bfloat16 h0, l0, h1, l1;
            split_bf(w0, h0, l0);
            split_bf(w1, h1, l1);
            *(uint32_t*)&wh[r * 264 + i * 64 + lane * 2] = pk(h0, h1);
            *(uint32_t*)&wl[r * 264 + i * 64 + lane * 2] = pk(l0, l1);
        }
    }
    __syncthreads();

    // ---- out = wei @ v : split-K over warps (2m x 2n x 4k) ----
    {
        const int wk = w & 3;
        const int wn2 = (w >> 2) & 1;
        const int wm2 = w >> 3;
        if (wk < nst) {
            const int arow = wm2 * 32 + (lane & 15);
            const int acol = (lane >> 4) * 8;
            const int vrow = (lane & 7) + ((lane >> 3) & 1) * 8;
            const int vcol = wn2 * 32 + (lane >> 4) * 8;
            float oacc[2][4][4] = {};
            #pragma unroll
            for (int ks = 0; ks < 4; ks++) {
                uint32_t aw[2][4], awl[2][4], bvh[2][4], bvl[2][4];
                #pragma unroll
                for (int mi = 0; mi < 2; mi++) {
                    uint32_t aoff = ((arow + mi * 16) * 264 + wk * 64 + ks * 16 + acol) * 2;
                    ldsm4(aw[mi],  wHa + aoff);
                    ldsm4(awl[mi], wLa + aoff);
                }
                #pragma unroll
                for (int nj = 0; nj < 2; nj++) {
                    uint32_t voff = ((wk * 64 + ks * 16 + vrow) * 72 + vcol + nj * 16) * 2;
                    ldsm4t(bvh[nj], kHa + voff);
                    ldsm4t(bvl[nj], kLa + voff);
                }
                #pragma unroll
                for (int mi = 0; mi < 2; mi++)
                    #pragma unroll
                    for (int ni = 0; ni < 4; ni++) {
                        const uint32_t* ph = &bvh[ni >> 1][(ni & 1) * 2];
                        const uint32_t* pl = &bvl[ni >> 1][(ni & 1) * 2];
                        mma_bf16(oacc[mi][ni], aw[mi],  ph);
                        mma_bf16(oacc[mi][ni], aw[mi],  pl);
                        mma_bf16(oacc[mi][ni], awl[mi], ph);
                    }
            }
            float* slice = sc + wk * 4096;
            #pragma unroll
            for (int mi = 0; mi < 2; mi++)
                #pragma unroll
                for (int ni = 0; ni < 4; ni++) {
                    int row = wm2 * 32 + mi * 16 + g;
                    int col = wn2 * 32 + ni * 8 + l2 * 2;
                    float2 o0 = {oacc[mi][ni][0], oacc[mi][ni][1]};
                    float2 o1 = {oacc[mi][ni][2], oacc[mi][ni][3]};
                    *(float2*)&slice[row * 64 + col] = o0;
                    *(float2*)&slice[(row + 8) * 64 + col] = o1;
                }
        }
    }
    __syncthreads();

    // ---- reduce nst slices and store ----
    #pragma unroll
    for (int i = 0; i < 8; i++) {
        int idx = tid + i * 512;
        float s = sc[idx];
        for (int j = 1; j < nst; j++) s += sc[j * 4096 + idx];
        int row = idx >> 6, col = idx & 63;
        out[((long)(b * Tn + t0 + row)) * Hn + col] = s;
    }
}

// ---------------------------------------------------------------------------
extern "C" void kernel_launch(void* const* d_in, const int* in_sizes, int n_in,
                              void* d_out, int out_size)
{
    const float* x  = (const float*)d_in[0];
    const float* Wk = (const float*)d_in[1];
    const float* Wq = (const float*)d_in[2];
    const float* Wv = (const float*)d_in[3];
    const float* E  = (const float*)d_in[4];
    float* out = (float*)d_out;

    setup_kernel<<<288, 256>>>(Wk, Wq, Wv, E);

    const int qkv_sm = (2 * 128 * 72 + 2 * 192 * 72) * (int)sizeof(__nv_bfloat16); // 92160
    cudaFuncSetAttribute(qkv_kernel, cudaFuncAttributeMaxDynamicSharedMemorySize, qkv_sm);
    qkv_kernel<<<Bn * Tn / 128, 512, qkv_sm>>>(x);

    const int attn_sm = 64 * 264 * 4 + 2 * 64 * 264 * 2 + 2 * 64 * 72 * 2
                      + 2 * 256 * 72 * 2;                                          // 227328
    cudaFuncSetAttribute(attn_kernel, cudaFuncAttributeMaxDynamicSharedMemorySize, attn_sm);
    attn_kernel<<<dim3(Bn, Tn / 64), 512, attn_sm>>>(out);
}